// round 5
// baseline (speedup 1.0000x reference)
#include <cuda_runtime.h>
#include <cstdint>

#define B_  1024
#define T_  32
#define D_  64
#define E_  100000
#define L_  50
#define NUM_BAGS (B_ * T_)        // 32768
#define THREADS 64                // 2 warps/CTA
#define WARPS_PER_CTA 2
#define CTAS 1184                 // 148 SMs * 8 resident CTAs -> persistent
#define TOTAL_WARPS (CTAS * WARPS_PER_CTA)   // 2368

// Persistent-warp pooled embedding gather.
// One warp owns a sequence of bags (grid-stride). Per bag:
//   - 25 cp.async.cg pair-loads (512B each; lanes 0-15 even row, 16-31 odd,
//     16B/lane) into a per-warp 12.8KB smem row buffer, 5 commit groups.
//   - While gathers are in flight, prefetch the NEXT bag's 50 indices
//     (2 coalesced LDGs -> STS into a double-buffered idx slot), hiding the
//     index-load latency that previously left the DRAM pipe idle per bag.
//   - Progressive wait_group + reduce overlaps the tail of the gathers.
// Bags remapped table-grouped (new_bag = t*1024+b) so the concurrent wave's
// footprint (~2.3 tables, ~24MB) fits L2 and repeated rows hit L2.

template<int N>
__device__ __forceinline__ void cp_wait_group() {
    asm volatile("cp.async.wait_group %0;\n" :: "n"(N) : "memory");
}

__global__ void __launch_bounds__(THREADS, 8)
embedding_bags_kernel(const float* __restrict__ weights,   // (E, T, D)
                      const int*   __restrict__ features,  // (B*T*L)
                      float*       __restrict__ out)       // (B*T, D)
{
    __shared__ __align__(16) float4 srows[WARPS_PER_CTA * L_ * 16]; // 25600B
    __shared__ int sidx[WARPS_PER_CTA * 2 * 64];                    // 1024B

    const int warp  = threadIdx.x >> 5;
    const int lane  = threadIdx.x & 31;
    const int half  = lane >> 4;           // 0: even row of pair, 1: odd
    const int sub   = lane & 15;           // 16B chunk within 256B row
    const int gwarp = blockIdx.x * WARPS_PER_CTA + warp;

    float4* __restrict__ sbuf = srows + warp * (L_ * 16);
    const uint32_t sbase = (uint32_t)__cvta_generic_to_shared(sbuf);
    int* __restrict__ idxbuf = sidx + warp * 128;   // two 64-int slots

    // ---- Preload indices for first bag into slot 0 ----
    {
        const int nb = gwarp;
        if (nb < NUM_BAGS) {
            const int t = nb >> 10, b = nb & 1023;
            const int* p = features + (size_t)((b << 5) | t) * L_;
            idxbuf[lane] = __ldg(p + lane);
            if (lane < (L_ - 32)) idxbuf[32 + lane] = __ldg(p + 32 + lane);
        }
    }
    __syncwarp();

    int cur = 0;
    for (int nb = gwarp; nb < NUM_BAGS; nb += TOTAL_WARPS) {
        const int t        = nb >> 10;
        const int b        = nb & 1023;
        const int bag_orig = (b << 5) | t;

        // row (idx, t) as float4: idx*(T*D/4) + t*(D/4) + sub
        const float4* __restrict__ gbase =
            reinterpret_cast<const float4*>(weights) + (size_t)t * (D_ / 4) + sub;

        const int* __restrict__ myidx = idxbuf + cur * 64;

        // ---- Issue 25 independent pair-loads in 5 commit groups ----
        #pragma unroll
        for (int g = 0; g < 5; ++g) {
            #pragma unroll
            for (int p = 0; p < 5; ++p) {
                const int r   = 2 * (g * 5 + p) + half;    // row slot 0..49
                const int idx = myidx[r];
                const float4* src = gbase + (size_t)idx * (T_ * D_ / 4);
                const uint32_t dst = sbase + (uint32_t)(r * 256 + sub * 16);
                asm volatile("cp.async.cg.shared.global [%0], [%1], 16;\n"
                             :: "r"(dst), "l"(src) : "memory");
            }
            asm volatile("cp.async.commit_group;\n" ::: "memory");
        }

        // ---- Prefetch next bag's indices into the other slot (overlapped) ----
        const int nnb = nb + TOTAL_WARPS;
        if (nnb < NUM_BAGS) {
            const int nt = nnb >> 10, nbb = nnb & 1023;
            const int* p = features + (size_t)((nbb << 5) | nt) * L_;
            int* dstbuf = idxbuf + (cur ^ 1) * 64;
            dstbuf[lane] = __ldg(p + lane);
            if (lane < (L_ - 32)) dstbuf[32 + lane] = __ldg(p + 32 + lane);
        }

        // ---- Progressive reduce; lanes read only bytes they wrote ----
        float4 acc = make_float4(0.0f, 0.0f, 0.0f, 0.0f);
#define REDUCE_GROUP(G)                                              \
        cp_wait_group<4 - (G)>();                                    \
        _Pragma("unroll")                                            \
        for (int p = 0; p < 5; ++p) {                                \
            const int r = 2 * ((G) * 5 + p) + half;                  \
            float4 v = sbuf[r * 16 + sub];                           \
            acc.x += v.x; acc.y += v.y; acc.z += v.z; acc.w += v.w;  \
        }
        REDUCE_GROUP(0)
        REDUCE_GROUP(1)
        REDUCE_GROUP(2)
        REDUCE_GROUP(3)
        REDUCE_GROUP(4)
#undef REDUCE_GROUP

        // Merge even-row half and odd-row half
        acc.x += __shfl_xor_sync(0xffffffffu, acc.x, 16);
        acc.y += __shfl_xor_sync(0xffffffffu, acc.y, 16);
        acc.z += __shfl_xor_sync(0xffffffffu, acc.z, 16);
        acc.w += __shfl_xor_sync(0xffffffffu, acc.w, 16);

        if (half == 0) {
            reinterpret_cast<float4*>(out)[(size_t)bag_orig * (D_ / 4) + sub] = acc;
        }

        cur ^= 1;
        __syncwarp();   // idx prefetch STS visible before next iteration reads
    }
}

extern "C" void kernel_launch(void* const* d_in, const int* in_sizes, int n_in,
                              void* d_out, int out_size)
{
    const float* weights  = (const float*)d_in[0];
    const int*   features = (const int*)  d_in[1];
    float* out = (float*)d_out;

    embedding_bags_kernel<<<CTAS, THREADS>>>(weights, features, out);
}

// round 8
// speedup vs baseline: 1.0256x; 1.0256x over previous
#include <cuda_runtime.h>
#include <cstdint>

#define B_  1024
#define T_  32
#define D_  64
#define E_  100000
#define L_  50
#define NUM_BAGS (B_ * T_)        // 32768
#define THREADS 64                // 2 warps/CTA
#define WPC 2
#define CTAS 1184                 // 148 SMs * 8 CTAs -> exactly one wave
#define TW (CTAS * WPC)           // 2368 warps

#define PAIRS_A 13                // rows 0..25
#define PAIRS_B 12                // rows 26..49

// Persistent warps with a cross-bag software pipeline over cp.async stages.
// Each bag = 25 row-pairs (pair = 2 rows x 256B, lanes 0-15 even row,
// 16-31 odd row, 16B/lane). Stage A (13 pairs) and stage B (12 pairs) are
// separate commit groups in separate smem buffers. Steady state:
//   issue B(i) -> wait<=1 -> reduce A(i) -> issue A(i+1) -> wait<=1
//   -> reduce B(i) -> merge/store
// so every warp always has >= 1 stage (6-13KB) of gathers in flight; the
// per-bag drain bubble of round 5 is gone. Indices are prefetched TWO bags
// ahead into a 4-slot smem ring, hiding their DRAM latency completely.
// Table-grouped bag remap (new_bag = t*1024 + b) keeps the concurrent
// footprint ~2.3 tables so repeated rows hit L2 (traffic already at the
// unique-row floor).

template<int N>
__device__ __forceinline__ void cp_wait_group() {
    asm volatile("cp.async.wait_group %0;\n" :: "n"(N) : "memory");
}
__device__ __forceinline__ void cp_commit() {
    asm volatile("cp.async.commit_group;\n" ::: "memory");
}
__device__ __forceinline__ void cp16(uint32_t dst, const void* src) {
    asm volatile("cp.async.cg.shared.global [%0], [%1], 16;\n"
                 :: "r"(dst), "l"(src) : "memory");
}

__global__ void __launch_bounds__(THREADS, 8)
embedding_bags_kernel(const float* __restrict__ weights,   // (E, T, D)
                      const int*   __restrict__ features,  // (B*T*L)
                      float*       __restrict__ out)       // (B*T, D)
{
    __shared__ __align__(16) float4 sA[WPC][PAIRS_A * 32];  // 13312B
    __shared__ __align__(16) float4 sB[WPC][PAIRS_B * 32];  // 12288B
    __shared__ int sidx[WPC][4][64];                        // 2048B

    const int warp = threadIdx.x >> 5;
    const int lane = threadIdx.x & 31;
    const int half = lane >> 4;            // 0: even row of pair, 1: odd
    const int sub  = lane & 15;            // 16B chunk within 256B row
    const int gwarp = blockIdx.x * WPC + warp;   // 0..2367 (< NUM_BAGS)

    float4* __restrict__ bufA = sA[warp];
    float4* __restrict__ bufB = sB[warp];
    const uint32_t aBase = (uint32_t)__cvta_generic_to_shared(bufA);
    const uint32_t bBase = (uint32_t)__cvta_generic_to_shared(bufB);

    auto load_idx = [&](int bag, int slot) {
        const int t = bag >> 10, b = bag & 1023;
        const int* p = features + (size_t)((b << 5) | t) * L_;
        sidx[warp][slot][lane] = __ldg(p + lane);
        if (lane < (L_ - 32)) sidx[warp][slot][32 + lane] = __ldg(p + 32 + lane);
    };
    auto make_gbase = [&](int bag) {
        const int t = bag >> 10;
        return reinterpret_cast<const float4*>(weights) + (size_t)t * (D_ / 4) + sub;
    };
    auto issueA = [&](int bag, int slot) {
        const float4* gb = make_gbase(bag);
        const int* ip = sidx[warp][slot];
        #pragma unroll
        for (int p = 0; p < PAIRS_A; ++p) {
            const int idx = ip[2 * p + half];
            cp16(aBase + (uint32_t)(p * 512 + half * 256 + sub * 16),
                 gb + (size_t)idx * (T_ * D_ / 4));
        }
        cp_commit();
    };
    auto issueB = [&](int bag, int slot) {
        const float4* gb = make_gbase(bag);
        const int* ip = sidx[warp][slot];
        #pragma unroll
        for (int p = 0; p < PAIRS_B; ++p) {
            const int idx = ip[2 * (PAIRS_A + p) + half];
            cp16(bBase + (uint32_t)(p * 512 + half * 256 + sub * 16),
                 gb + (size_t)idx * (T_ * D_ / 4));
        }
        cp_commit();
    };

    // ---- Prologue: idx(bag0), issue A(bag0), idx(bag1) ----
    int slot = 0;
    int nb = gwarp;
    load_idx(nb, 0);
    __syncwarp();
    issueA(nb, 0);
    if (nb + TW < NUM_BAGS) load_idx(nb + TW, 1);
    __syncwarp();

    for (; nb < NUM_BAGS; nb += TW) {
        const bool has_next = (nb + TW) < NUM_BAGS;

        issueB(nb, slot);
        if (nb + 2 * TW < NUM_BAGS) load_idx(nb + 2 * TW, (slot + 2) & 3);

        cp_wait_group<1>();                  // stage A(nb) complete
        float4 acc = make_float4(0.0f, 0.0f, 0.0f, 0.0f);
        #pragma unroll
        for (int p = 0; p < PAIRS_A; ++p) {
            float4 v = bufA[p * 32 + half * 16 + sub];
            acc.x += v.x; acc.y += v.y; acc.z += v.z; acc.w += v.w;
        }

        __syncwarp();                        // idx prefetch STS visible
        if (has_next) { issueA(nb + TW, (slot + 1) & 3); cp_wait_group<1>(); }
        else          { cp_wait_group<0>(); }
        // now stage B(nb) complete (A(nb+TW) may still be in flight)
        #pragma unroll
        for (int p = 0; p < PAIRS_B; ++p) {
            float4 v = bufB[p * 32 + half * 16 + sub];
            acc.x += v.x; acc.y += v.y; acc.z += v.z; acc.w += v.w;
        }

        acc.x += __shfl_xor_sync(0xffffffffu, acc.x, 16);
        acc.y += __shfl_xor_sync(0xffffffffu, acc.y, 16);
        acc.z += __shfl_xor_sync(0xffffffffu, acc.z, 16);
        acc.w += __shfl_xor_sync(0xffffffffu, acc.w, 16);

        const int t = nb >> 10, b = nb & 1023;
        const int bag_orig = (b << 5) | t;
        if (half == 0) {
            reinterpret_cast<float4*>(out)[(size_t)bag_orig * (D_ / 4) + sub] = acc;
        }
        slot = (slot + 1) & 3;
    }
}

extern "C" void kernel_launch(void* const* d_in, const int* in_sizes, int n_in,
                              void* d_out, int out_size)
{
    const float* weights  = (const float*)d_in[0];
    const int*   features = (const int*)  d_in[1];
    float* out = (float*)d_out;

    embedding_bags_kernel<<<CTAS, THREADS>>>(weights, features, out);
}

// round 9
// speedup vs baseline: 1.0619x; 1.0354x over previous
#include <cuda_runtime.h>
#include <cstdint>

#define B_  1024
#define T_  32
#define D_  64
#define E_  100000
#define L_  50
#define NUM_BAGS (B_ * T_)        // 32768
#define THREADS 64
#define BAGS_PER_CTA 2

// Round-4 winning structure (best measured: 57.5us, DRAM 76.2% = the random
// 256B-granule DRAM efficiency ceiling; traffic already at the compulsory
// unique-row floor). This revision only trims per-bag overhead:
//  - 50 indices staged with ONE LDG.64 (25 lanes x int2) + one STS.64
//  - 25 cp.async.cg pair-loads (512B each: lanes 0-15 even row, 16-31 odd,
//    16B/lane) in 5 commit groups, progressive wait+reduce.
// Table-grouped bag remap keeps the concurrent wave inside ~2 tables so all
// repeated rows hit L2.

template<int N>
__device__ __forceinline__ void cp_wait_group() {
    asm volatile("cp.async.wait_group %0;\n" :: "n"(N) : "memory");
}

__global__ void __launch_bounds__(THREADS, 8)
embedding_bags_kernel(const float* __restrict__ weights,   // (E, T, D)
                      const int*   __restrict__ features,  // (B*T*L)
                      float*       __restrict__ out)       // (B*T, D)
{
    __shared__ __align__(16) float4 srows[BAGS_PER_CTA * L_ * 16]; // 25600B
    __shared__ __align__(8)  int2   sidx2[BAGS_PER_CTA * 32];      // 512B

    const int warp = threadIdx.x >> 5;
    const int lane = threadIdx.x & 31;
    const int half = lane >> 4;            // 0: even row of pair, 1: odd
    const int sub  = lane & 15;            // 16B chunk within 256B row

    // Table-grouped remap: new_bag = t*1024 + b  ->  orig bag = b*32 + t
    const int new_bag  = blockIdx.x * BAGS_PER_CTA + warp;
    const int t        = new_bag >> 10;
    const int b        = new_bag & 1023;
    const int bag_orig = (b << 5) | t;

    // Stage 50 indices: 25 lanes each load one int2 (8B aligned: 200B*bag).
    const int2* __restrict__ idxp2 =
        reinterpret_cast<const int2*>(features + (size_t)bag_orig * L_);
    int2* __restrict__ myidx2 = sidx2 + warp * 32;
    if (lane < 25) myidx2[lane] = __ldg(idxp2 + lane);
    __syncwarp();
    const int* __restrict__ myidx = reinterpret_cast<const int*>(myidx2);

    // row (idx, t) as float4: idx*(T*D/4) + t*(D/4) + sub
    const float4* __restrict__ gbase =
        reinterpret_cast<const float4*>(weights) + (size_t)t * (D_ / 4) + sub;

    float4* __restrict__ sbuf = srows + warp * (L_ * 16);
    const uint32_t sbase = (uint32_t)__cvta_generic_to_shared(sbuf);

    // Issue 25 independent pair-loads in 5 commit groups
    #pragma unroll
    for (int g = 0; g < 5; ++g) {
        #pragma unroll
        for (int p = 0; p < 5; ++p) {
            const int r   = 2 * (g * 5 + p) + half;   // row slot 0..49
            const int idx = myidx[r];
            const float4* src = gbase + (size_t)idx * (T_ * D_ / 4);
            const uint32_t dst = sbase + (uint32_t)(r * 256 + sub * 16);
            asm volatile("cp.async.cg.shared.global [%0], [%1], 16;\n"
                         :: "r"(dst), "l"(src) : "memory");
        }
        asm volatile("cp.async.commit_group;\n" ::: "memory");
    }

    float4 acc = make_float4(0.0f, 0.0f, 0.0f, 0.0f);

    // Progressive reduce; each lane reads only bytes it wrote itself.
#define REDUCE_GROUP(G)                                              \
    cp_wait_group<4 - (G)>();                                        \
    _Pragma("unroll")                                                \
    for (int p = 0; p < 5; ++p) {                                    \
        const int r = 2 * ((G) * 5 + p) + half;                      \
        float4 v = sbuf[r * 16 + sub];                               \
        acc.x += v.x; acc.y += v.y; acc.z += v.z; acc.w += v.w;      \
    }

    REDUCE_GROUP(0)
    REDUCE_GROUP(1)
    REDUCE_GROUP(2)
    REDUCE_GROUP(3)
    REDUCE_GROUP(4)
#undef REDUCE_GROUP

    // Merge even-row half and odd-row half
    acc.x += __shfl_xor_sync(0xffffffffu, acc.x, 16);
    acc.y += __shfl_xor_sync(0xffffffffu, acc.y, 16);
    acc.z += __shfl_xor_sync(0xffffffffu, acc.z, 16);
    acc.w += __shfl_xor_sync(0xffffffffu, acc.w, 16);

    if (half == 0) {
        reinterpret_cast<float4*>(out)[(size_t)bag_orig * (D_ / 4) + sub] = acc;
    }
}

extern "C" void kernel_launch(void* const* d_in, const int* in_sizes, int n_in,
                              void* d_out, int out_size)
{
    const float* weights  = (const float*)d_in[0];
    const int*   features = (const int*)  d_in[1];
    float* out = (float*)d_out;

    const int blocks = NUM_BAGS / BAGS_PER_CTA;   // 16384
    embedding_bags_kernel<<<blocks, THREADS>>>(weights, features, out);
}

// round 11
// speedup vs baseline: 1.0625x; 1.0006x over previous
#include <cuda_runtime.h>
#include <cstdint>

#define B_  1024
#define T_  32
#define D_  64
#define E_  100000
#define L_  50
#define NUM_BAGS (B_ * T_)        // 32768
#define THREADS 64
#define BAGS_PER_CTA 2

// Best-measured structure (round 4: 57.5us, DRAM 76% = random-256B-granule
// efficiency ceiling; traffic at the compulsory unique-row floor).
// Micro-trims this round (resubmitted after infra failure in round 10):
//  - output stored with st.global.cs (evict-first: don't let 8.4MB of output
//    write-allocate displace table rows from L2)
//  - index loads with ld.global.cs (streaming, zero reuse)
// Everything else proven: one warp per bag, 25 cp.async.cg pair-loads
// (512B each; lanes 0-15 even row, 16-31 odd, 16B/lane) in 5 commit groups,
// progressive wait+reduce, table-grouped bag remap for L2 reuse.

template<int N>
__device__ __forceinline__ void cp_wait_group() {
    asm volatile("cp.async.wait_group %0;\n" :: "n"(N) : "memory");
}

__device__ __forceinline__ int2 ldg_cs_int2(const int2* p) {
    int2 v;
    asm volatile("ld.global.cs.v2.s32 {%0,%1}, [%2];\n"
                 : "=r"(v.x), "=r"(v.y) : "l"(p));
    return v;
}

__device__ __forceinline__ void stg_cs_float4(float4* p, float4 v) {
    asm volatile("st.global.cs.v4.f32 [%0], {%1,%2,%3,%4};\n"
                 :: "l"(p), "f"(v.x), "f"(v.y), "f"(v.z), "f"(v.w) : "memory");
}

__global__ void __launch_bounds__(THREADS, 8)
embedding_bags_kernel(const float* __restrict__ weights,   // (E, T, D)
                      const int*   __restrict__ features,  // (B*T*L)
                      float*       __restrict__ out)       // (B*T, D)
{
    __shared__ __align__(16) float4 srows[BAGS_PER_CTA * L_ * 16]; // 25600B
    __shared__ __align__(8)  int2   sidx2[BAGS_PER_CTA * 32];      // 512B

    const int warp = threadIdx.x >> 5;
    const int lane = threadIdx.x & 31;
    const int half = lane >> 4;            // 0: even row of pair, 1: odd
    const int sub  = lane & 15;            // 16B chunk within 256B row

    // Table-grouped remap: new_bag = t*1024 + b  ->  orig bag = b*32 + t
    const int new_bag  = blockIdx.x * BAGS_PER_CTA + warp;
    const int t        = new_bag >> 10;
    const int b        = new_bag & 1023;
    const int bag_orig = (b << 5) | t;

    // Stage 50 indices: 25 lanes each load one int2 (8B aligned: 200B/bag).
    const int2* __restrict__ idxp2 =
        reinterpret_cast<const int2*>(features + (size_t)bag_orig * L_);
    int2* __restrict__ myidx2 = sidx2 + warp * 32;
    if (lane < 25) myidx2[lane] = ldg_cs_int2(idxp2 + lane);
    __syncwarp();
    const int* __restrict__ myidx = reinterpret_cast<const int*>(myidx2);

    // row (idx, t) as float4: idx*(T*D/4) + t*(D/4) + sub
    const float4* __restrict__ gbase =
        reinterpret_cast<const float4*>(weights) + (size_t)t * (D_ / 4) + sub;

    float4* __restrict__ sbuf = srows + warp * (L_ * 16);
    const uint32_t sbase = (uint32_t)__cvta_generic_to_shared(sbuf);

    // Issue 25 independent pair-loads in 5 commit groups
    #pragma unroll
    for (int g = 0; g < 5; ++g) {
        #pragma unroll
        for (int p = 0; p < 5; ++p) {
            const int r   = 2 * (g * 5 + p) + half;   // row slot 0..49
            const int idx = myidx[r];
            const float4* src = gbase + (size_t)idx * (T_ * D_ / 4);
            const uint32_t dst = sbase + (uint32_t)(r * 256 + sub * 16);
            asm volatile("cp.async.cg.shared.global [%0], [%1], 16;\n"
                         :: "r"(dst), "l"(src) : "memory");
        }
        asm volatile("cp.async.commit_group;\n" ::: "memory");
    }

    float4 acc = make_float4(0.0f, 0.0f, 0.0f, 0.0f);

    // Progressive reduce; each lane reads only bytes it wrote itself.
#define REDUCE_GROUP(G)                                              \
    cp_wait_group<4 - (G)>();                                        \
    _Pragma("unroll")                                                \
    for (int p = 0; p < 5; ++p) {                                    \
        const int r = 2 * ((G) * 5 + p) + half;                      \
        float4 v = sbuf[r * 16 + sub];                               \
        acc.x += v.x; acc.y += v.y; acc.z += v.z; acc.w += v.w;      \
    }

    REDUCE_GROUP(0)
    REDUCE_GROUP(1)
    REDUCE_GROUP(2)
    REDUCE_GROUP(3)
    REDUCE_GROUP(4)
#undef REDUCE_GROUP

    // Merge even-row half and odd-row half
    acc.x += __shfl_xor_sync(0xffffffffu, acc.x, 16);
    acc.y += __shfl_xor_sync(0xffffffffu, acc.y, 16);
    acc.z += __shfl_xor_sync(0xffffffffu, acc.z, 16);
    acc.w += __shfl_xor_sync(0xffffffffu, acc.w, 16);

    if (half == 0) {
        stg_cs_float4(reinterpret_cast<float4*>(out) +
                      (size_t)bag_orig * (D_ / 4) + sub, acc);
    }
}

extern "C" void kernel_launch(void* const* d_in, const int* in_sizes, int n_in,
                              void* d_out, int out_size)
{
    const float* weights  = (const float*)d_in[0];
    const int*   features = (const int*)  d_in[1];
    float* out = (float*)d_out;

    const int blocks = NUM_BAGS / BAGS_PER_CTA;   // 16384
    embedding_bags_kernel<<<blocks, THREADS>>>(weights, features, out);
}